// round 16
// baseline (speedup 1.0000x reference)
#include <cuda_runtime.h>
#include <cuda_fp16.h>

#define E_    4096
#define NN_   2048
#define D_    256
#define H_    8
#define DH_   32

// ---------------- scratch (device globals; no allocation allowed) ----------
__device__ __half g_cath[(size_t)E_ * 768];
__device__ __half g_h1h [(size_t)E_ * 256];
__device__ __half g_hh  [(size_t)E_ * 256];
__device__ __half g_qkh [(size_t)E_ * 512];        // [e][0:256)=Q(scaled) [256:512)=K
__device__ __half g_vh  [(size_t)H_ * 32 * E_];    // [h][dim][e]  (V transposed)
__device__ __half g_oh  [(size_t)E_ * 256];
__device__ float  g_node[NN_ * D_];
__device__ float  g_y   [NN_ * D_];
__device__ __half g_yh  [NN_ * D_];
__device__ float  g_z   [NN_ * D_];
__device__ unsigned g_mbits[(size_t)E_ * E_ / 32]; // bit-packed mask (2MB)
// half weights (pre-converted; root pre-transposed to [n][k])
__device__ __half g_w1h  [256 * 768];
__device__ __half g_w2h  [256 * 256];
__device__ __half g_ipwh [768 * 256];
__device__ __half g_owh  [256 * 256];
__device__ __half g_lwh  [256 * 256];
__device__ __half g_rooth[256 * 256];
__device__ __half g_xh   [NN_ * 256];

// ---------------- helpers ----------------------------------------------------
__device__ __forceinline__ void mma_f16(float* c,
                                        unsigned a0, unsigned a1,
                                        unsigned a2, unsigned a3,
                                        unsigned b0, unsigned b1) {
    asm volatile(
        "mma.sync.aligned.m16n8k16.row.col.f32.f16.f16.f32 "
        "{%0,%1,%2,%3}, {%4,%5,%6,%7}, {%8,%9}, {%0,%1,%2,%3};\n"
        : "+f"(c[0]), "+f"(c[1]), "+f"(c[2]), "+f"(c[3])
        : "r"(a0), "r"(a1), "r"(a2), "r"(a3), "r"(b0), "r"(b1));
}

__device__ __forceinline__ void cp16(void* dst_smem, const void* src_gmem) {
    unsigned d = (unsigned)__cvta_generic_to_shared(dst_smem);
    asm volatile("cp.async.cg.shared.global [%0], [%1], 16;\n"
                 :: "r"(d), "l"(src_gmem) : "memory");
}
__device__ __forceinline__ void cp_commit() {
    asm volatile("cp.async.commit_group;\n" ::: "memory");
}
__device__ __forceinline__ void cp_wait0() {
    asm volatile("cp.async.wait_group 0;\n" ::: "memory");
}
__device__ __forceinline__ void cp_wait1() {
    asm volatile("cp.async.wait_group 1;\n" ::: "memory");
}
__device__ __forceinline__ void cp_wait2() {
    asm volatile("cp.async.wait_group 2;\n" ::: "memory");
}

// ---------------- one-time prep: weights + x -> half ------------------------
__global__ void prep_kernel(const float* __restrict__ W1, const float* __restrict__ W2,
                            const float* __restrict__ ipw, const float* __restrict__ ow,
                            const float* __restrict__ lw, const float* __restrict__ root,
                            const float* __restrict__ x,
                            __half* __restrict__ w1h, __half* __restrict__ w2h,
                            __half* __restrict__ ipwh, __half* __restrict__ owh,
                            __half* __restrict__ lwh, __half* __restrict__ rooth,
                            __half* __restrict__ xh) {
    int idx = blockIdx.x * 256 + threadIdx.x;
    if (idx < 196608) {
        w1h[idx] = __float2half(W1[idx]);
    } else if (idx < 262144) {
        int i = idx - 196608; w2h[i] = __float2half(W2[i]);
    } else if (idx < 458752) {
        int i = idx - 262144; ipwh[i] = __float2half(ipw[i]);
    } else if (idx < 524288) {
        int i = idx - 458752; owh[i] = __float2half(ow[i]);
    } else if (idx < 589824) {
        int i = idx - 524288; lwh[i] = __float2half(lw[i]);
    } else if (idx < 655360) {
        int i = idx - 589824; int n = i >> 8, k = i & 255;
        rooth[i] = __float2half(root[k * 256 + n]);   // transpose [k][n]->[n][k]
    } else {
        int i = idx - 655360; xh[i] = __float2half(x[i]);
    }
}

// ---------------- mask -> bitpack (format auto-detected) --------------------
__global__ void mask_bits_kernel(const unsigned* __restrict__ mw,
                                 unsigned* __restrict__ mb) {
    __shared__ int cnt[4];
    if (threadIdx.x < 4) cnt[threadIdx.x] = 0;
    __syncthreads();
    if (threadIdx.x < 64) {
        unsigned w = mw[threadIdx.x];
        if      (w == 0x01010101u) atomicAdd(&cnt[0], 1);  // u8 bool
        else if (w == 0x3F800000u) atomicAdd(&cnt[1], 1);  // float32
        else if (w == 0x00000001u) atomicAdd(&cnt[2], 1);  // int32
        else if (w == 0x3F803F80u) atomicAdd(&cnt[3], 1);  // bf16
    }
    __syncthreads();
    int fmt = 0, best = cnt[0];
    if (cnt[1] > best) { best = cnt[1]; fmt = 1; }
    if (cnt[2] > best) { best = cnt[2]; fmt = 2; }
    if (cnt[3] > best) { best = cnt[3]; fmt = 3; }

    size_t w = (size_t)blockIdx.x * blockDim.x + threadIdx.x;
    unsigned bits = 0;
    if (fmt == 0) {
        const uchar4* p = (const uchar4*)((const unsigned char*)mw + w * 32);
#pragma unroll
        for (int j = 0; j < 8; j++) {
            uchar4 v = p[j];
            bits |= (unsigned)(v.x != 0) << (j * 4);
            bits |= (unsigned)(v.y != 0) << (j * 4 + 1);
            bits |= (unsigned)(v.z != 0) << (j * 4 + 2);
            bits |= (unsigned)(v.w != 0) << (j * 4 + 3);
        }
    } else if (fmt == 1 || fmt == 2) {
        const uint4* p = (const uint4*)(mw + w * 32);
#pragma unroll
        for (int j = 0; j < 8; j++) {
            uint4 v = p[j];
            bits |= (unsigned)(v.x != 0) << (j * 4);
            bits |= (unsigned)(v.y != 0) << (j * 4 + 1);
            bits |= (unsigned)(v.z != 0) << (j * 4 + 2);
            bits |= (unsigned)(v.w != 0) << (j * 4 + 3);
        }
    } else {
        const ushort4* p = (const ushort4*)((const unsigned short*)mw + w * 32);
#pragma unroll
        for (int j = 0; j < 8; j++) {
            ushort4 v = p[j];
            bits |= (unsigned)(v.x != 0) << (j * 4);
            bits |= (unsigned)(v.y != 0) << (j * 4 + 1);
            bits |= (unsigned)(v.z != 0) << (j * 4 + 2);
            bits |= (unsigned)(v.w != 0) << (j * 4 + 3);
        }
    }
    mb[w] = bits;
}

// ---------------- gather: cat_h = [x_i, x_j, edge_attr] as half ------------
__global__ void gather_cat_kernel(const float* __restrict__ x,
                                  const int* __restrict__ ei,
                                  const float* __restrict__ ea,
                                  __half* __restrict__ cat) {
    int e = blockIdx.x;
    int t = threadIdx.x;
    int sec = t >> 6, i = (t & 63) << 2;
    const float* src;
    if (sec == 0)      src = x  + (size_t)ei[E_ + e] * 256;  // x_i (target)
    else if (sec == 1) src = x  + (size_t)ei[e] * 256;       // x_j (source)
    else               src = ea + (size_t)e * 256;
    float4 v = *(const float4*)&src[i];
    __half* dst = &cat[(size_t)e * 768 + sec * 256 + i];
    *(__half2*)&dst[0] = __floats2half2_rn(v.x, v.y);
    *(__half2*)&dst[2] = __floats2half2_rn(v.z, v.w);
}

// ---------------- fp16 GEMM: all-half, cp.async 4-stage ring, 1 sync/iter --
template <bool LRELU, bool SCATTER, bool QKVOUT, bool HOUT>
__global__ void __launch_bounds__(256)
hgemm_kernel(const __half* __restrict__ A,
             const __half* __restrict__ Bh,
             const float* __restrict__ bias,
             float* __restrict__ C,
             __half* __restrict__ Ch,
             int M, int N, int K,
             const int* __restrict__ ei,
             __half* __restrict__ qkh,
             __half* __restrict__ vh) {
    __shared__ __half As[4][64][40];
    __shared__ __half Bs[4][64][40];

    int tid  = threadIdx.x;
    int warp = tid >> 5, lane = tid & 31;
    int warpm = warp >> 1, warpn = warp & 1;
    int g = lane >> 2, ti = lane & 3;
    int row0 = blockIdx.y * 64;
    int col0 = blockIdx.x * 64;

    int sr = tid >> 2, sc = (tid & 3) * 8;
    const __half* Ab = A  + (size_t)(row0 + sr) * K + sc;
    const __half* Bb = Bh + (size_t)(col0 + sr) * K + sc;

    float acc[4][4];
#pragma unroll
    for (int n = 0; n < 4; n++)
#pragma unroll
        for (int j = 0; j < 4; j++) acc[n][j] = 0.0f;

    int nit = K >> 5;
    cp16(&As[0][sr][sc], Ab);      cp16(&Bs[0][sr][sc], Bb);      cp_commit();
    cp16(&As[1][sr][sc], Ab + 32); cp16(&Bs[1][sr][sc], Bb + 32); cp_commit();
    cp16(&As[2][sr][sc], Ab + 64); cp16(&Bs[2][sr][sc], Bb + 64); cp_commit();

    for (int it = 0; it < nit; it++) {
        int st = it & 3;
        if (it + 2 < nit)      cp_wait2();
        else if (it + 1 < nit) cp_wait1();
        else                   cp_wait0();
        __syncthreads();

        if (it + 3 < nit) {
            int kk = (it + 3) * 32;
            int sn = (it + 3) & 3;
            cp16(&As[sn][sr][sc], Ab + kk);
            cp16(&Bs[sn][sr][sc], Bb + kk);
            cp_commit();
        }

#pragma unroll
        for (int ks = 0; ks < 2; ks++) {
            unsigned a0 = *(unsigned*)&As[st][warpm * 16 + g][ks * 16 + 2 * ti];
            unsigned a1 = *(unsigned*)&As[st][warpm * 16 + g + 8][ks * 16 + 2 * ti];
            unsigned a2 = *(unsigned*)&As[st][warpm * 16 + g][ks * 16 + 2 * ti + 8];
            unsigned a3 = *(unsigned*)&As[st][warpm * 16 + g + 8][ks * 16 + 2 * ti + 8];
#pragma unroll
            for (int n = 0; n < 4; n++) {
                unsigned b0 = *(unsigned*)&Bs[st][warpn * 32 + n * 8 + g][ks * 16 + 2 * ti];
                unsigned b1 = *(unsigned*)&Bs[st][warpn * 32 + n * 8 + g][ks * 16 + 2 * ti + 8];
                mma_f16(acc[n], a0, a1, a2, a3, b0, b1);
            }
        }
    }

    int r0 = row0 + warpm * 16 + g;
    int r1 = r0 + 8;
    if (SCATTER) {
        int t0 = ei[E_ + r0];
        int t1 = ei[E_ + r1];
#pragma unroll
        for (int n = 0; n < 4; n++) {
            int col = col0 + warpn * 32 + n * 8 + 2 * ti;
            float bx = bias[col], by = bias[col + 1];
            atomicAdd(&C[(size_t)t0 * N + col],     acc[n][0] + bx);
            atomicAdd(&C[(size_t)t0 * N + col + 1], acc[n][1] + by);
            atomicAdd(&C[(size_t)t1 * N + col],     acc[n][2] + bx);
            atomicAdd(&C[(size_t)t1 * N + col + 1], acc[n][3] + by);
        }
    } else if (QKVOUT) {
        const float qs = 0.17677669529663687f;   // 1/sqrt(32)
#pragma unroll
        for (int n = 0; n < 4; n++) {
            int col = col0 + warpn * 32 + n * 8 + 2 * ti;
            float bx = bias[col], by = bias[col + 1];
            float v0 = acc[n][0] + bx, v1 = acc[n][1] + by;
            float v2 = acc[n][2] + bx, v3 = acc[n][3] + by;
            if (col < 256) { v0 *= qs; v1 *= qs; v2 *= qs; v3 *= qs; }
            if (col < 512) {
                *(__half2*)&qkh[(size_t)r0 * 512 + col] = __floats2half2_rn(v0, v1);
                *(__half2*)&qkh[(size_t)r1 * 512 + col] = __floats2half2_rn(v2, v3);
            } else {
                int d = col - 512;
                size_t rowbase = (size_t)d * 4096;   // vh[d][e]
                vh[rowbase + r0]        = __float2half(v0);
                vh[rowbase + 4096 + r0] = __float2half(v1);
                vh[rowbase + r1]        = __float2half(v2);
                vh[rowbase + 4096 + r1] = __float2half(v3);
            }
        }
    } else if (HOUT) {
#pragma unroll
        for (int n = 0; n < 4; n++) {
            int col = col0 + warpn * 32 + n * 8 + 2 * ti;
            float bx = bias[col], by = bias[col + 1];
            float v0 = acc[n][0] + bx, v1 = acc[n][1] + by;
            float v2 = acc[n][2] + bx, v3 = acc[n][3] + by;
            if (LRELU) {
                v0 = v0 > 0.0f ? v0 : 0.2f * v0;
                v1 = v1 > 0.0f ? v1 : 0.2f * v1;
                v2 = v2 > 0.0f ? v2 : 0.2f * v2;
                v3 = v3 > 0.0f ? v3 : 0.2f * v3;
            }
            *(__half2*)&Ch[(size_t)r0 * N + col] = __floats2half2_rn(v0, v1);
            *(__half2*)&Ch[(size_t)r1 * N + col] = __floats2half2_rn(v2, v3);
        }
    } else {
#pragma unroll
        for (int n = 0; n < 4; n++) {
            int col = col0 + warpn * 32 + n * 8 + 2 * ti;
            float bx = bias[col], by = bias[col + 1];
            float v0 = acc[n][0] + bx, v1 = acc[n][1] + by;
            float v2 = acc[n][2] + bx, v3 = acc[n][3] + by;
            *(float2*)&C[(size_t)r0 * N + col] = make_float2(v0, v1);
            *(float2*)&C[(size_t)r1 * N + col] = make_float2(v2, v3);
        }
    }
}

// ---------------- flash attention: 64 queries / 4 warps / 128 threads ------
// Same per-warp structure as R13 (16 queries/warp, fp16 k16, cp.async ring)
// but 512 blocks -> 4-6 blocks/SM (16-24 warps/SM) for latency hiding.
// smem 33792 B.
__global__ void __launch_bounds__(128, 4)
flash_attn_mma_kernel(const __half* __restrict__ qkh,
                      const __half* __restrict__ vh,
                      const unsigned* __restrict__ mbits,
                      __half* __restrict__ o) {
    extern __shared__ char smc[];
    __half (*Qs)[40]     = (__half(*)[40])smc;                 // 64 x 40  (5120B)
    __half (*Ks)[64][40] = (__half(*)[64][40])(smc + 5120);    // 2 x 64 x 40 (10240B)
    __half (*Vs)[32][72] = (__half(*)[32][72])(smc + 15360);   // 2 x 32 x 72 (9216B)
    __half (*Ps)[72]     = (__half(*)[72])(smc + 24576);       // 64 x 72 (9216B)

    int tid  = threadIdx.x;
    int warp = tid >> 5, lane = tid & 31;
    int g = lane >> 2, ti = lane & 3;
    int q0 = blockIdx.x * 64;
    int h  = blockIdx.y;

    // per-thread staging: 2 chunks each of K and V (16B chunks)
    int kr[2], kc[2], vr[2], vc[2];
#pragma unroll
    for (int i = 0; i < 2; i++) {
        int id = i * 128 + tid;
        kr[i] = id >> 2; kc[i] = (id & 3) * 8;     // K: 64 rows x 32 halves
        vr[i] = id >> 3; vc[i] = (id & 7) * 8;     // V: 32 rows x 64 halves
    }

    // prologue: Q (2 chunks) + K/V tile 0
#pragma unroll
    for (int i = 0; i < 2; i++) {
        int id = i * 128 + tid;
        int qr = id >> 2, qc = (id & 3) * 8;
        cp16(&Qs[qr][qc], qkh + (size_t)(q0 + qr) * 512 + h * 32 + qc);
    }
#pragma unroll
    for (int i = 0; i < 2; i++) {
        cp16(&Ks[0][kr[i]][kc[i]], qkh + (size_t)kr[i] * 512 + 256 + h * 32 + kc[i]);
        cp16(&Vs[0][vr[i]][vc[i]], vh + (size_t)(h * 32 + vr[i]) * 4096 + vc[i]);
    }
    cp_commit();
    cp_wait0();
    __syncthreads();

    int qrow = warp * 16;
    unsigned qa[2][4];
#pragma unroll
    for (int ks = 0; ks < 2; ks++) {
        qa[ks][0] = *(unsigned*)&Qs[qrow + g][ks * 16 + 2 * ti];
        qa[ks][1] = *(unsigned*)&Qs[qrow + g + 8][ks * 16 + 2 * ti];
        qa[ks][2] = *(unsigned*)&Qs[qrow + g][ks * 16 + 2 * ti + 8];
        qa[ks][3] = *(unsigned*)&Qs[qrow + g + 8][ks * 16 + 2 * ti + 8];
    }

    float l0 = 0.0f, l1 = 0.0f;
    float oacc[4][4];
#pragma unroll
    for (int n = 0; n < 4; n++)
#pragma unroll
        for (int j = 0; j < 4; j++) oacc[n][j] = 0.0f;

    const unsigned* mrow0 = mbits + (size_t)(q0 + qrow + g) * 128;
    const unsigned* mrow1 = mrow0 + 8 * 128;

    for (int kb = 0; kb < 64; kb++) {
        int cur = kb & 1;

        // issue next tile into the other stage (overlaps compute)
        if (kb < 63) {
            int kk = (kb + 1) * 64;
            int nxt = cur ^ 1;
#pragma unroll
            for (int i = 0; i < 2; i++) {
                cp16(&Ks[nxt][kr[i]][kc[i]],
                     qkh + (size_t)(kk + kr[i]) * 512 + 256 + h * 32 + kc[i]);
                cp16(&Vs[nxt][vr[i]][vc[i]],
                     vh + (size_t)(h * 32 + vr[i]) * 4096 + kk + vc[i]);
            }
            cp_commit();
        }

        // ---- S = Q K^T (fp16 k16) ----
        float sacc[8][4];
#pragma unroll
        for (int n = 0; n < 8; n++)
#pragma unroll
            for (int j = 0; j < 4; j++) sacc[n][j] = 0.0f;

#pragma unroll
        for (int ks = 0; ks < 2; ks++) {
#pragma unroll
            for (int n = 0; n < 8; n++) {
                unsigned b0 = *(unsigned*)&Ks[cur][n * 8 + g][ks * 16 + 2 * ti];
                unsigned b1 = *(unsigned*)&Ks[cur][n * 8 + g][ks * 16 + 2 * ti + 8];
                mma_f16(sacc[n], qa[ks][0], qa[ks][1], qa[ks][2], qa[ks][3], b0, b1);
            }
        }

        // ---- mask + exp + P store (half2) + running sums ----
        {
            uint2 wa = *(const uint2*)&mrow0[kb * 2];
            uint2 wb = *(const uint2*)&mrow1[kb * 2];
            unsigned long long ma = (unsigned long long)wa.x |
                                    ((unsigned long long)wa.y << 32);
            unsigned long long mbv = (unsigned long long)wb.x |
                                     ((unsigned long long)wb.y << 32);
#pragma unroll
            for (int n = 0; n < 8; n++) {
                int b = n * 8 + 2 * ti;
                float p0 = ((ma  >> b) & 1)       ? __expf(sacc[n][0]) : 0.0f;
                float p1 = ((ma  >> (b + 1)) & 1) ? __expf(sacc[n][1]) : 0.0f;
                float p2 = ((mbv >> b) & 1)       ? __expf(sacc[n][2]) : 0.0f;
                float p3 = ((mbv >> (b + 1)) & 1) ? __expf(sacc[n][3]) : 0.0f;
                l0 += p0 + p1;
                l1 += p2 + p3;
                *(__half2*)&Ps[qrow + g][n * 8 + 2 * ti]     = __floats2half2_rn(p0, p1);
                *(__half2*)&Ps[qrow + g + 8][n * 8 + 2 * ti] = __floats2half2_rn(p2, p3);
            }
        }
        __syncwarp();

        // ---- O += P V (fp16 k16; V transposed [dim][key]) ----
#pragma unroll
        for (int ks = 0; ks < 4; ks++) {
            unsigned pa0 = *(unsigned*)&Ps[qrow + g][ks * 16 + 2 * ti];
            unsigned pa1 = *(unsigned*)&Ps[qrow + g + 8][ks * 16 + 2 * ti];
            unsigned pa2 = *(unsigned*)&Ps[qrow + g][ks * 16 + 2 * ti + 8];
            unsigned pa3 = *(unsigned*)&Ps[qrow + g + 8][ks * 16 + 2 * ti + 8];
#pragma unroll
            for (int n = 0; n < 4; n++) {
                unsigned b0 = *(unsigned*)&Vs[cur][n * 8 + g][ks * 16 + 2 * ti];
                unsigned b1 = *(unsigned*)&Vs[cur][n * 8 + g][ks * 16 + 2 * ti + 8];
                mma_f16(oacc[n], pa0, pa1, pa2, pa3, b0, b1);
            }
        }

        cp_wait0();        // next tile landed
        __syncthreads();   // visible to all; this tile fully consumed
    }

#pragma unroll
    for (int off = 1; off <= 2; off <<= 1) {
        l0 += __shfl_xor_sync(0xffffffffu, l0, off);
        l1 += __shfl_xor_sync(0xffffffffu, l1, off);
    }
    float inv0 = 1.0f / l0, inv1 = 1.0f / l1;
#pragma unroll
    for (int n = 0; n < 4; n++) {
        int d = h * 32 + n * 8 + 2 * ti;
        *(__half2*)&o[(size_t)(q0 + qrow + g) * 256 + d] =
            __floats2half2_rn(oacc[n][0] * inv0, oacc[n][1] * inv0);
        *(__half2*)&o[(size_t)(q0 + qrow + g + 8) * 256 + d] =
            __floats2half2_rn(oacc[n][2] * inv1, oacc[n][3] * inv1);
    }
}

// ---------------- layernorm --------------------------------------------------
__device__ __forceinline__ float block_sum256(float v, float* sbuf) {
#pragma unroll
    for (int off = 16; off; off >>= 1) v += __shfl_xor_sync(0xffffffffu, v, off);
    int w = threadIdx.x >> 5;
    if ((threadIdx.x & 31) == 0) sbuf[w] = v;
    __syncthreads();
    if (threadIdx.x < 8) {
        float t = sbuf[threadIdx.x];
#pragma unroll
        for (int off = 4; off; off >>= 1) t += __shfl_xor_sync(0xffu, t, off);
        if (threadIdx.x == 0) sbuf[0] = t;
    }
    __syncthreads();
    float r = sbuf[0];
    __syncthreads();
    return r;
}

// LN1: writes fp32 y (residual path) AND half y_h (GEMM input)
__global__ void ln_kernel(const float* __restrict__ in,
                          const float* __restrict__ g,
                          const float* __restrict__ b,
                          float* __restrict__ out,
                          __half* __restrict__ outh) {
    __shared__ float sbuf[8];
    int row = blockIdx.x, t = threadIdx.x;
    float v = in[(size_t)row * 256 + t];
    float mu = block_sum256(v, sbuf) * (1.0f / 256.0f);
    float dv = v - mu;
    float var = block_sum256(dv * dv, sbuf) * (1.0f / 256.0f);
    float r = dv * rsqrtf(var + 1e-5f) * g[t] + b[t];
    out[(size_t)row * 256 + t] = r;
    outh[(size_t)row * 256 + t] = __float2half(r);
}

__global__ void ln_add_kernel(const float* __restrict__ in1,
                              const float* __restrict__ in2,
                              const float* __restrict__ g,
                              const float* __restrict__ b,
                              float* __restrict__ out) {
    __shared__ float sbuf[8];
    int row = blockIdx.x, t = threadIdx.x;
    float v = in1[(size_t)row * 256 + t] + in2[(size_t)row * 256 + t];
    float mu = block_sum256(v, sbuf) * (1.0f / 256.0f);
    float dv = v - mu;
    float var = block_sum256(dv * dv, sbuf) * (1.0f / 256.0f);
    out[(size_t)row * 256 + t] = dv * rsqrtf(var + 1e-5f) * g[t] + b[t];
}

// ---------------- launch ----------------------------------------------------
extern "C" void kernel_launch(void* const* d_in, const int* in_sizes, int n_in,
                              void* d_out, int out_size) {
    const float* x    = (const float*)d_in[0];
    const int*   ei   = (const int*)d_in[1];
    const float* ea   = (const float*)d_in[2];
    const unsigned* mask_raw = (const unsigned*)d_in[3];
    const float* W1   = (const float*)d_in[4];
    const float* b1   = (const float*)d_in[5];
    const float* W2   = (const float*)d_in[6];
    const float* b2   = (const float*)d_in[7];
    const float* ipw  = (const float*)d_in[8];
    const float* ipb  = (const float*)d_in[9];
    const float* ow   = (const float*)d_in[10];
    const float* ob   = (const float*)d_in[11];
    const float* root = (const float*)d_in[12];
    const float* bp   = (const float*)d_in[13];
    const float* l1g  = (const float*)d_in[14];
    const float* l1b  = (const float*)d_in[15];
    const float* l2g  = (const float*)d_in[16];
    const float* l2b  = (const float*)d_in[17];
    const float* lw   = (const float*)d_in[18];
    const float* lb   = (const float*)d_in[19];
    float* out = (float*)d_out;

    __half *cath, *h1h, *hh, *qkh, *vh, *oh, *yh;
    __half *w1h, *w2h, *ipwh, *owh, *lwh, *rooth, *xh;
    float *node, *y, *z;
    unsigned* mb;
    cudaGetSymbolAddress((void**)&cath,  g_cath);
    cudaGetSymbolAddress((void**)&h1h,   g_h1h);
    cudaGetSymbolAddress((void**)&hh,    g_hh);
    cudaGetSymbolAddress((void**)&qkh,   g_qkh);
    cudaGetSymbolAddress((void**)&vh,    g_vh);
    cudaGetSymbolAddress((void**)&oh,    g_oh);
    cudaGetSymbolAddress((void**)&node,  g_node);
    cudaGetSymbolAddress((void**)&y,     g_y);
    cudaGetSymbolAddress((void**)&yh,    g_yh);
    cudaGetSymbolAddress((void**)&z,     g_z);
    cudaGetSymbolAddress((void**)&mb,    g_mbits);
    cudaGetSymbolAddress((void**)&w1h,   g_w1h);
    cudaGetSymbolAddress((void**)&w2h,   g_w2h);
    cudaGetSymbolAddress((void**)&ipwh,  g_ipwh);
    cudaGetSymbolAddress((void**)&owh,   g_owh);
    cudaGetSymbolAddress((void**)&lwh,   g_lwh);
    cudaGetSymbolAddress((void**)&rooth, g_rooth);
    cudaGetSymbolAddress((void**)&xh,    g_xh);

    const int FLASH_SMEM = 33792;
    cudaFuncSetAttribute(flash_attn_mma_kernel,
                         cudaFuncAttributeMaxDynamicSharedMemorySize, FLASH_SMEM);

    prep_kernel<<<4608, 256>>>(W1, W2, ipw, ow, lw, root, x,
                               w1h, w2h, ipwh, owh, lwh, rooth, xh);
    mask_bits_kernel<<<(E_ * E_ / 32) / 256, 256>>>(mask_raw, mb);
    gather_cat_kernel<<<E_, 192>>>(x, ei, ea, cath);

    // h1 = lrelu(cat @ W1^T + b1)  -> half
    hgemm_kernel<true,  false, false, true ><<<dim3(4, 64), 256>>>(
        cath, w1h, b1, 0, h1h, E_, 256, 768, 0, 0, 0);
    // h = h1 @ W2^T + b2  -> half
    hgemm_kernel<false, false, false, true ><<<dim3(4, 64), 256>>>(
        h1h, w2h, b2, 0, hh, E_, 256, 256, 0, 0, 0);
    // qkv -> qkh (Q scaled + K), vh (V transposed)
    hgemm_kernel<false, false, true,  false><<<dim3(12, 64), 256>>>(
        hh, ipwh, ipb, 0, 0, E_, 768, 256, 0, qkh, vh);

    flash_attn_mma_kernel<<<dim3(64, 8), 128, FLASH_SMEM>>>(qkh, vh, mb, oh);

    // node = x @ root + bias_p  (root pre-transposed; plain fp32 stores)
    hgemm_kernel<false, false, false, false><<<dim3(4, 32), 256>>>(
        xh, rooth, bp, node, 0, NN_, 256, 256, 0, 0, 0);
    // node[ei[1][e]] += o @ out_w^T + out_b   (fused scatter)
    hgemm_kernel<false, true,  false, false><<<dim3(4, 64), 256>>>(
        oh, owh, ob, node, 0, E_, 256, 256, ei, 0, 0);

    ln_kernel<<<NN_, 256>>>(node, l1g, l1b, y, yh);
    // z = y @ lin_w^T + lin_b
    hgemm_kernel<false, false, false, false><<<dim3(4, 32), 256>>>(
        yh, lwh, lb, z, 0, NN_, 256, 256, 0, 0, 0);
    ln_add_kernel<<<NN_, 256>>>(y, z, l2g, l2b, out);
}

// round 17
// speedup vs baseline: 1.0282x; 1.0282x over previous
#include <cuda_runtime.h>
#include <cuda_fp16.h>

#define E_    4096
#define NN_   2048
#define D_    256
#define H_    8
#define DH_   32

// ---------------- scratch (device globals; no allocation allowed) ----------
__device__ __half g_cath[(size_t)E_ * 768];
__device__ __half g_h1h [(size_t)E_ * 256];
__device__ __half g_hh  [(size_t)E_ * 256];
__device__ __half g_qkh [(size_t)E_ * 512];        // [e][0:256)=Q(scaled) [256:512)=K
__device__ __half g_vh  [(size_t)H_ * 32 * E_];    // [h][dim][e]  (V transposed)
__device__ __half g_oh  [(size_t)E_ * 256];
__device__ float  g_node[NN_ * D_];
__device__ float  g_y   [NN_ * D_];
__device__ __half g_yh  [NN_ * D_];
__device__ float  g_z   [NN_ * D_];
__device__ unsigned g_mbits[(size_t)E_ * E_ / 32]; // bit-packed mask (2MB)
// half weights (pre-converted; root pre-transposed to [n][k])
__device__ __half g_w1h  [256 * 768];
__device__ __half g_w2h  [256 * 256];
__device__ __half g_ipwh [768 * 256];
__device__ __half g_owh  [256 * 256];
__device__ __half g_lwh  [256 * 256];
__device__ __half g_rooth[256 * 256];
__device__ __half g_xh   [NN_ * 256];

// ---------------- helpers ----------------------------------------------------
__device__ __forceinline__ void mma_f16(float* c,
                                        unsigned a0, unsigned a1,
                                        unsigned a2, unsigned a3,
                                        unsigned b0, unsigned b1) {
    asm volatile(
        "mma.sync.aligned.m16n8k16.row.col.f32.f16.f16.f32 "
        "{%0,%1,%2,%3}, {%4,%5,%6,%7}, {%8,%9}, {%0,%1,%2,%3};\n"
        : "+f"(c[0]), "+f"(c[1]), "+f"(c[2]), "+f"(c[3])
        : "r"(a0), "r"(a1), "r"(a2), "r"(a3), "r"(b0), "r"(b1));
}

__device__ __forceinline__ void cp16(void* dst_smem, const void* src_gmem) {
    unsigned d = (unsigned)__cvta_generic_to_shared(dst_smem);
    asm volatile("cp.async.cg.shared.global [%0], [%1], 16;\n"
                 :: "r"(d), "l"(src_gmem) : "memory");
}
__device__ __forceinline__ void cp_commit() {
    asm volatile("cp.async.commit_group;\n" ::: "memory");
}
__device__ __forceinline__ void cp_wait0() {
    asm volatile("cp.async.wait_group 0;\n" ::: "memory");
}
__device__ __forceinline__ void cp_wait1() {
    asm volatile("cp.async.wait_group 1;\n" ::: "memory");
}
__device__ __forceinline__ void cp_wait2() {
    asm volatile("cp.async.wait_group 2;\n" ::: "memory");
}

// ---------------- fused prep (weights+x -> half) AND mask bitpack ----------
// blocks [0, 4608): elementwise half conversion of weights/x.
// blocks [4608, 6656): mask -> bit words (format auto-detected by voting).
__global__ void prep_mask_kernel(const float* __restrict__ W1, const float* __restrict__ W2,
                                 const float* __restrict__ ipw, const float* __restrict__ ow,
                                 const float* __restrict__ lw, const float* __restrict__ root,
                                 const float* __restrict__ x,
                                 __half* __restrict__ w1h, __half* __restrict__ w2h,
                                 __half* __restrict__ ipwh, __half* __restrict__ owh,
                                 __half* __restrict__ lwh, __half* __restrict__ rooth,
                                 __half* __restrict__ xh,
                                 const unsigned* __restrict__ mw,
                                 unsigned* __restrict__ mb) {
    if (blockIdx.x < 4608) {
        int idx = blockIdx.x * 256 + threadIdx.x;
        if (idx < 196608) {
            w1h[idx] = __float2half(W1[idx]);
        } else if (idx < 262144) {
            int i = idx - 196608; w2h[i] = __float2half(W2[i]);
        } else if (idx < 458752) {
            int i = idx - 262144; ipwh[i] = __float2half(ipw[i]);
        } else if (idx < 524288) {
            int i = idx - 458752; owh[i] = __float2half(ow[i]);
        } else if (idx < 589824) {
            int i = idx - 524288; lwh[i] = __float2half(lw[i]);
        } else if (idx < 655360) {
            int i = idx - 589824; int n = i >> 8, k = i & 255;
            rooth[i] = __float2half(root[k * 256 + n]);   // transpose
        } else {
            int i = idx - 655360; xh[i] = __float2half(x[i]);
        }
        return;
    }

    // ---- mask bitpack ----
    __shared__ int cnt[4];
    if (threadIdx.x < 4) cnt[threadIdx.x] = 0;
    __syncthreads();
    if (threadIdx.x < 64) {
        unsigned w = mw[threadIdx.x];
        if      (w == 0x01010101u) atomicAdd(&cnt[0], 1);  // u8 bool
        else if (w == 0x3F800000u) atomicAdd(&cnt[1], 1);  // float32
        else if (w == 0x00000001u) atomicAdd(&cnt[2], 1);  // int32
        else if (w == 0x3F803F80u) atomicAdd(&cnt[3], 1);  // bf16
    }
    __syncthreads();
    int fmt = 0, best = cnt[0];
    if (cnt[1] > best) { best = cnt[1]; fmt = 1; }
    if (cnt[2] > best) { best = cnt[2]; fmt = 2; }
    if (cnt[3] > best) { best = cnt[3]; fmt = 3; }

    size_t w = (size_t)(blockIdx.x - 4608) * 256 + threadIdx.x;  // word index
    unsigned bits = 0;
    if (fmt == 0) {
        const uchar4* p = (const uchar4*)((const unsigned char*)mw + w * 32);
#pragma unroll
        for (int j = 0; j < 8; j++) {
            uchar4 v = p[j];
            bits |= (unsigned)(v.x != 0) << (j * 4);
            bits |= (unsigned)(v.y != 0) << (j * 4 + 1);
            bits |= (unsigned)(v.z != 0) << (j * 4 + 2);
            bits |= (unsigned)(v.w != 0) << (j * 4 + 3);
        }
    } else if (fmt == 1 || fmt == 2) {
        const uint4* p = (const uint4*)(mw + w * 32);
#pragma unroll
        for (int j = 0; j < 8; j++) {
            uint4 v = p[j];
            bits |= (unsigned)(v.x != 0) << (j * 4);
            bits |= (unsigned)(v.y != 0) << (j * 4 + 1);
            bits |= (unsigned)(v.z != 0) << (j * 4 + 2);
            bits |= (unsigned)(v.w != 0) << (j * 4 + 3);
        }
    } else {
        const ushort4* p = (const ushort4*)((const unsigned short*)mw + w * 32);
#pragma unroll
        for (int j = 0; j < 8; j++) {
            ushort4 v = p[j];
            bits |= (unsigned)(v.x != 0) << (j * 4);
            bits |= (unsigned)(v.y != 0) << (j * 4 + 1);
            bits |= (unsigned)(v.z != 0) << (j * 4 + 2);
            bits |= (unsigned)(v.w != 0) << (j * 4 + 3);
        }
    }
    mb[w] = bits;
}

// ---------------- gather: cat_h = [x_i, x_j, edge_attr] as half ------------
__global__ void gather_cat_kernel(const float* __restrict__ x,
                                  const int* __restrict__ ei,
                                  const float* __restrict__ ea,
                                  __half* __restrict__ cat) {
    int e = blockIdx.x;
    int t = threadIdx.x;
    int sec = t >> 6, i = (t & 63) << 2;
    const float* src;
    if (sec == 0)      src = x  + (size_t)ei[E_ + e] * 256;  // x_i (target)
    else if (sec == 1) src = x  + (size_t)ei[e] * 256;       // x_j (source)
    else               src = ea + (size_t)e * 256;
    float4 v = *(const float4*)&src[i];
    __half* dst = &cat[(size_t)e * 768 + sec * 256 + i];
    *(__half2*)&dst[0] = __floats2half2_rn(v.x, v.y);
    *(__half2*)&dst[2] = __floats2half2_rn(v.z, v.w);
}

// ---------------- fp16 GEMM: all-half, cp.async 4-stage ring, 1 sync/iter --
template <bool LRELU, bool SCATTER, bool QKVOUT, bool HOUT>
__global__ void __launch_bounds__(256)
hgemm_kernel(const __half* __restrict__ A,
             const __half* __restrict__ Bh,
             const float* __restrict__ bias,
             float* __restrict__ C,
             __half* __restrict__ Ch,
             int M, int N, int K,
             const int* __restrict__ ei,
             __half* __restrict__ qkh,
             __half* __restrict__ vh) {
    __shared__ __half As[4][64][40];
    __shared__ __half Bs[4][64][40];

    int tid  = threadIdx.x;
    int warp = tid >> 5, lane = tid & 31;
    int warpm = warp >> 1, warpn = warp & 1;
    int g = lane >> 2, ti = lane & 3;
    int row0 = blockIdx.y * 64;
    int col0 = blockIdx.x * 64;

    int sr = tid >> 2, sc = (tid & 3) * 8;
    const __half* Ab = A  + (size_t)(row0 + sr) * K + sc;
    const __half* Bb = Bh + (size_t)(col0 + sr) * K + sc;

    float acc[4][4];
#pragma unroll
    for (int n = 0; n < 4; n++)
#pragma unroll
        for (int j = 0; j < 4; j++) acc[n][j] = 0.0f;

    int nit = K >> 5;
    cp16(&As[0][sr][sc], Ab);      cp16(&Bs[0][sr][sc], Bb);      cp_commit();
    cp16(&As[1][sr][sc], Ab + 32); cp16(&Bs[1][sr][sc], Bb + 32); cp_commit();
    cp16(&As[2][sr][sc], Ab + 64); cp16(&Bs[2][sr][sc], Bb + 64); cp_commit();

    for (int it = 0; it < nit; it++) {
        int st = it & 3;
        if (it + 2 < nit)      cp_wait2();
        else if (it + 1 < nit) cp_wait1();
        else                   cp_wait0();
        __syncthreads();

        if (it + 3 < nit) {
            int kk = (it + 3) * 32;
            int sn = (it + 3) & 3;
            cp16(&As[sn][sr][sc], Ab + kk);
            cp16(&Bs[sn][sr][sc], Bb + kk);
            cp_commit();
        }

#pragma unroll
        for (int ks = 0; ks < 2; ks++) {
            unsigned a0 = *(unsigned*)&As[st][warpm * 16 + g][ks * 16 + 2 * ti];
            unsigned a1 = *(unsigned*)&As[st][warpm * 16 + g + 8][ks * 16 + 2 * ti];
            unsigned a2 = *(unsigned*)&As[st][warpm * 16 + g][ks * 16 + 2 * ti + 8];
            unsigned a3 = *(unsigned*)&As[st][warpm * 16 + g + 8][ks * 16 + 2 * ti + 8];
#pragma unroll
            for (int n = 0; n < 4; n++) {
                unsigned b0 = *(unsigned*)&Bs[st][warpn * 32 + n * 8 + g][ks * 16 + 2 * ti];
                unsigned b1 = *(unsigned*)&Bs[st][warpn * 32 + n * 8 + g][ks * 16 + 2 * ti + 8];
                mma_f16(acc[n], a0, a1, a2, a3, b0, b1);
            }
        }
    }

    int r0 = row0 + warpm * 16 + g;
    int r1 = r0 + 8;
    if (SCATTER) {
        int t0 = ei[E_ + r0];
        int t1 = ei[E_ + r1];
#pragma unroll
        for (int n = 0; n < 4; n++) {
            int col = col0 + warpn * 32 + n * 8 + 2 * ti;
            float bx = bias[col], by = bias[col + 1];
            atomicAdd(&C[(size_t)t0 * N + col],     acc[n][0] + bx);
            atomicAdd(&C[(size_t)t0 * N + col + 1], acc[n][1] + by);
            atomicAdd(&C[(size_t)t1 * N + col],     acc[n][2] + bx);
            atomicAdd(&C[(size_t)t1 * N + col + 1], acc[n][3] + by);
        }
    } else if (QKVOUT) {
        const float qs = 0.17677669529663687f;   // 1/sqrt(32)
#pragma unroll
        for (int n = 0; n < 4; n++) {
            int col = col0 + warpn * 32 + n * 8 + 2 * ti;
            float bx = bias[col], by = bias[col + 1];
            float v0 = acc[n][0] + bx, v1 = acc[n][1] + by;
            float v2 = acc[n][2] + bx, v3 = acc[n][3] + by;
            if (col < 256) { v0 *= qs; v1 *= qs; v2 *= qs; v3 *= qs; }
            if (col < 512) {
                *(__half2*)&qkh[(size_t)r0 * 512 + col] = __floats2half2_rn(v0, v1);
                *(__half2*)&qkh[(size_t)r1 * 512 + col] = __floats2half2_rn(v2, v3);
            } else {
                int d = col - 512;
                size_t rowbase = (size_t)d * 4096;   // vh[d][e]
                vh[rowbase + r0]        = __float2half(v0);
                vh[rowbase + 4096 + r0] = __float2half(v1);
                vh[rowbase + r1]        = __float2half(v2);
                vh[rowbase + 4096 + r1] = __float2half(v3);
            }
        }
    } else if (HOUT) {
#pragma unroll
        for (int n = 0; n < 4; n++) {
            int col = col0 + warpn * 32 + n * 8 + 2 * ti;
            float bx = bias[col], by = bias[col + 1];
            float v0 = acc[n][0] + bx, v1 = acc[n][1] + by;
            float v2 = acc[n][2] + bx, v3 = acc[n][3] + by;
            if (LRELU) {
                v0 = v0 > 0.0f ? v0 : 0.2f * v0;
                v1 = v1 > 0.0f ? v1 : 0.2f * v1;
                v2 = v2 > 0.0f ? v2 : 0.2f * v2;
                v3 = v3 > 0.0f ? v3 : 0.2f * v3;
            }
            *(__half2*)&Ch[(size_t)r0 * N + col] = __floats2half2_rn(v0, v1);
            *(__half2*)&Ch[(size_t)r1 * N + col] = __floats2half2_rn(v2, v3);
        }
    } else {
#pragma unroll
        for (int n = 0; n < 4; n++) {
            int col = col0 + warpn * 32 + n * 8 + 2 * ti;
            float bx = bias[col], by = bias[col + 1];
            float v0 = acc[n][0] + bx, v1 = acc[n][1] + by;
            float v2 = acc[n][2] + bx, v3 = acc[n][3] + by;
            *(float2*)&C[(size_t)r0 * N + col] = make_float2(v0, v1);
            *(float2*)&C[(size_t)r1 * N + col] = make_float2(v2, v3);
        }
    }
}

// ---------------- flash attention: fp16 mma (k16), cp.async staging --------
// (R15 structure — the best measured variant; launch #6 so ncu captures it.)
__global__ void __launch_bounds__(256, 2)
flash_attn_mma_kernel(const __half* __restrict__ qkh,
                      const __half* __restrict__ vh,
                      const unsigned* __restrict__ mbits,
                      __half* __restrict__ o) {
    extern __shared__ char smc[];
    __half (*Qs)[40]     = (__half(*)[40])smc;                 // 128 x 40
    __half (*Ks)[64][40] = (__half(*)[64][40])(smc + 10240);   // 2 x 64 x 40
    __half (*Vs)[32][72] = (__half(*)[32][72])(smc + 20480);   // 2 x 32 x 72
    __half (*Ps)[72]     = (__half(*)[72])(smc + 29696);       // 128 x 72

    int tid  = threadIdx.x;
    int warp = tid >> 5, lane = tid & 31;
    int g = lane >> 2, ti = lane & 3;
    int q0 = blockIdx.x * 128;
    int h  = blockIdx.y;

    int kr = tid >> 2, kc = (tid & 3) * 8;
    int vr = tid >> 3, vc = (tid & 7) * 8;

#pragma unroll
    for (int i = 0; i < 2; i++) {
        int id = i * 256 + tid;
        int qr = id >> 2, qc = (id & 3) * 8;
        cp16(&Qs[qr][qc], qkh + (size_t)(q0 + qr) * 512 + h * 32 + qc);
    }
    cp16(&Ks[0][kr][kc], qkh + (size_t)kr * 512 + 256 + h * 32 + kc);
    cp16(&Vs[0][vr][vc], vh + (size_t)(h * 32 + vr) * 4096 + vc);
    cp_commit();
    cp_wait0();
    __syncthreads();

    int qrow = warp * 16;
    unsigned qa[2][4];
#pragma unroll
    for (int ks = 0; ks < 2; ks++) {
        qa[ks][0] = *(unsigned*)&Qs[qrow + g][ks * 16 + 2 * ti];
        qa[ks][1] = *(unsigned*)&Qs[qrow + g + 8][ks * 16 + 2 * ti];
        qa[ks][2] = *(unsigned*)&Qs[qrow + g][ks * 16 + 2 * ti + 8];
        qa[ks][3] = *(unsigned*)&Qs[qrow + g + 8][ks * 16 + 2 * ti + 8];
    }

    float l0 = 0.0f, l1 = 0.0f;
    float oacc[4][4];
#pragma unroll
    for (int n = 0; n < 4; n++)
#pragma unroll
        for (int j = 0; j < 4; j++) oacc[n][j] = 0.0f;

    const unsigned* mrow0 = mbits + (size_t)(q0 + qrow + g) * 128;
    const unsigned* mrow1 = mrow0 + 8 * 128;

    for (int kb = 0; kb < 64; kb++) {
        int cur = kb & 1;

        if (kb < 63) {
            int kk = (kb + 1) * 64;
            int nxt = cur ^ 1;
            cp16(&Ks[nxt][kr][kc], qkh + (size_t)(kk + kr) * 512 + 256 + h * 32 + kc);
            cp16(&Vs[nxt][vr][vc], vh + (size_t)(h * 32 + vr) * 4096 + kk + vc);
            cp_commit();
        }

        float sacc[8][4];
#pragma unroll
        for (int n = 0; n < 8; n++)
#pragma unroll
            for (int j = 0; j < 4; j++) sacc[n][j] = 0.0f;

#pragma unroll
        for (int ks = 0; ks < 2; ks++) {
#pragma unroll
            for (int n = 0; n < 8; n++) {
                unsigned b0 = *(unsigned*)&Ks[cur][n * 8 + g][ks * 16 + 2 * ti];
                unsigned b1 = *(unsigned*)&Ks[cur][n * 8 + g][ks * 16 + 2 * ti + 8];
                mma_f16(sacc[n], qa[ks][0], qa[ks][1], qa[ks][2], qa[ks][3], b0, b1);
            }
        }

        {
            uint2 wa = *(const uint2*)&mrow0[kb * 2];
            uint2 wb = *(const uint2*)&mrow1[kb * 2];
            unsigned long long ma = (unsigned long long)wa.x |
                                    ((unsigned long long)wa.y << 32);
            unsigned long long mbv = (unsigned long long)wb.x |
                                     ((unsigned long long)wb.y << 32);
#pragma unroll
            for (int n = 0; n < 8; n++) {
                int b = n * 8 + 2 * ti;
                float p0 = ((ma  >> b) & 1)       ? __expf(sacc[n][0]) : 0.0f;
                float p1 = ((ma  >> (b + 1)) & 1) ? __expf(sacc[n][1]) : 0.0f;
                float p2 = ((mbv >> b) & 1)       ? __expf(sacc[n][2]) : 0.0f;
                float p3 = ((mbv >> (b + 1)) & 1) ? __expf(sacc[n][3]) : 0.0f;
                l0 += p0 + p1;
                l1 += p2 + p3;
                *(__half2*)&Ps[qrow + g][n * 8 + 2 * ti]     = __floats2half2_rn(p0, p1);
                *(__half2*)&Ps[qrow + g + 8][n * 8 + 2 * ti] = __floats2half2_rn(p2, p3);
            }
        }
        __syncwarp();

#pragma unroll
        for (int ks = 0; ks < 4; ks++) {
            unsigned pa0 = *(unsigned*)&Ps[qrow + g][ks * 16 + 2 * ti];
            unsigned pa1 = *(unsigned*)&Ps[qrow + g + 8][ks * 16 + 2 * ti];
            unsigned pa2 = *(unsigned*)&Ps[qrow + g][ks * 16 + 2 * ti + 8];
            unsigned pa3 = *(unsigned*)&Ps[qrow + g + 8][ks * 16 + 2 * ti + 8];
#pragma unroll
            for (int n = 0; n < 4; n++) {
                unsigned b0 = *(unsigned*)&Vs[cur][n * 8 + g][ks * 16 + 2 * ti];
                unsigned b1 = *(unsigned*)&Vs[cur][n * 8 + g][ks * 16 + 2 * ti + 8];
                mma_f16(oacc[n], pa0, pa1, pa2, pa3, b0, b1);
            }
        }

        cp_wait0();
        __syncthreads();
    }

#pragma unroll
    for (int off = 1; off <= 2; off <<= 1) {
        l0 += __shfl_xor_sync(0xffffffffu, l0, off);
        l1 += __shfl_xor_sync(0xffffffffu, l1, off);
    }
    float inv0 = 1.0f / l0, inv1 = 1.0f / l1;
#pragma unroll
    for (int n = 0; n < 4; n++) {
        int d = h * 32 + n * 8 + 2 * ti;
        *(__half2*)&o[(size_t)(q0 + qrow + g) * 256 + d] =
            __floats2half2_rn(oacc[n][0] * inv0, oacc[n][1] * inv0);
        *(__half2*)&o[(size_t)(q0 + qrow + g + 8) * 256 + d] =
            __floats2half2_rn(oacc[n][2] * inv1, oacc[n][3] * inv1);
    }
}

// ---------------- layernorm --------------------------------------------------
__device__ __forceinline__ float block_sum256(float v, float* sbuf) {
#pragma unroll
    for (int off = 16; off; off >>= 1) v += __shfl_xor_sync(0xffffffffu, v, off);
    int w = threadIdx.x >> 5;
    if ((threadIdx.x & 31) == 0) sbuf[w] = v;
    __syncthreads();
    if (threadIdx.x < 8) {
        float t = sbuf[threadIdx.x];
#pragma unroll
        for (int off = 4; off; off >>= 1) t += __shfl_xor_sync(0xffu, t, off);
        if (threadIdx.x == 0) sbuf[0] = t;
    }
    __syncthreads();
    float r = sbuf[0];
    __syncthreads();
    return r;
}

// LN1: writes fp32 y (residual path) AND half y_h (GEMM input)
__global__ void ln_kernel(const float* __restrict__ in,
                          const float* __restrict__ g,
                          const float* __restrict__ b,
                          float* __restrict__ out,
                          __half* __restrict__ outh) {
    __shared__ float sbuf[8];
    int row = blockIdx.x, t = threadIdx.x;
    float v = in[(size_t)row * 256 + t];
    float mu = block_sum256(v, sbuf) * (1.0f / 256.0f);
    float dv = v - mu;
    float var = block_sum256(dv * dv, sbuf) * (1.0f / 256.0f);
    float r = dv * rsqrtf(var + 1e-5f) * g[t] + b[t];
    out[(size_t)row * 256 + t] = r;
    outh[(size_t)row * 256 + t] = __float2half(r);
}

__global__ void ln_add_kernel(const float* __restrict__ in1,
                              const float* __restrict__ in2,
                              const float* __restrict__ g,
                              const float* __restrict__ b,
                              float* __restrict__ out) {
    __shared__ float sbuf[8];
    int row = blockIdx.x, t = threadIdx.x;
    float v = in1[(size_t)row * 256 + t] + in2[(size_t)row * 256 + t];
    float mu = block_sum256(v, sbuf) * (1.0f / 256.0f);
    float dv = v - mu;
    float var = block_sum256(dv * dv, sbuf) * (1.0f / 256.0f);
    out[(size_t)row * 256 + t] = dv * rsqrtf(var + 1e-5f) * g[t] + b[t];
}

// ---------------- launch ----------------------------------------------------
extern "C" void kernel_launch(void* const* d_in, const int* in_sizes, int n_in,
                              void* d_out, int out_size) {
    const float* x    = (const float*)d_in[0];
    const int*   ei   = (const int*)d_in[1];
    const float* ea   = (const float*)d_in[2];
    const unsigned* mask_raw = (const unsigned*)d_in[3];
    const float* W1   = (const float*)d_in[4];
    const float* b1   = (const float*)d_in[5];
    const float* W2   = (const float*)d_in[6];
    const float* b2   = (const float*)d_in[7];
    const float* ipw  = (const float*)d_in[8];
    const float* ipb  = (const float*)d_in[9];
    const float* ow   = (const float*)d_in[10];
    const float* ob   = (const float*)d_in[11];
    const float* root = (const float*)d_in[12];
    const float* bp   = (const float*)d_in[13];
    const float* l1g  = (const float*)d_in[14];
    const float* l1b  = (const float*)d_in[15];
    const float* l2g  = (const float*)d_in[16];
    const float* l2b  = (const float*)d_in[17];
    const float* lw   = (const float*)d_in[18];
    const float* lb   = (const float*)d_in[19];
    float* out = (float*)d_out;

    __half *cath, *h1h, *hh, *qkh, *vh, *oh, *yh;
    __half *w1h, *w2h, *ipwh, *owh, *lwh, *rooth, *xh;
    float *node, *y, *z;
    unsigned* mb;
    cudaGetSymbolAddress((void**)&cath,  g_cath);
    cudaGetSymbolAddress((void**)&h1h,   g_h1h);
    cudaGetSymbolAddress((void**)&hh,    g_hh);
    cudaGetSymbolAddress((void**)&qkh,   g_qkh);
    cudaGetSymbolAddress((void**)&vh,    g_vh);
    cudaGetSymbolAddress((void**)&oh,    g_oh);
    cudaGetSymbolAddress((void**)&node,  g_node);
    cudaGetSymbolAddress((void**)&y,     g_y);
    cudaGetSymbolAddress((void**)&yh,    g_yh);
    cudaGetSymbolAddress((void**)&z,     g_z);
    cudaGetSymbolAddress((void**)&mb,    g_mbits);
    cudaGetSymbolAddress((void**)&w1h,   g_w1h);
    cudaGetSymbolAddress((void**)&w2h,   g_w2h);
    cudaGetSymbolAddress((void**)&ipwh,  g_ipwh);
    cudaGetSymbolAddress((void**)&owh,   g_owh);
    cudaGetSymbolAddress((void**)&lwh,   g_lwh);
    cudaGetSymbolAddress((void**)&rooth, g_rooth);
    cudaGetSymbolAddress((void**)&xh,    g_xh);

    const int FLASH_SMEM = 48128;
    cudaFuncSetAttribute(flash_attn_mma_kernel,
                         cudaFuncAttributeMaxDynamicSharedMemorySize, FLASH_SMEM);

    // launch #1: fused weight/x conversion + mask bitpack
    prep_mask_kernel<<<4608 + 2048, 256>>>(W1, W2, ipw, ow, lw, root, x,
                                           w1h, w2h, ipwh, owh, lwh, rooth, xh,
                                           mask_raw, mb);
    // #2
    gather_cat_kernel<<<E_, 192>>>(x, ei, ea, cath);

    // #3: h1 = lrelu(cat @ W1^T + b1)
    hgemm_kernel<true,  false, false, true ><<<dim3(4, 64), 256>>>(
        cath, w1h, b1, 0, h1h, E_, 256, 768, 0, 0, 0);
    // #4: h = h1 @ W2^T + b2
    hgemm_kernel<false, false, false, true ><<<dim3(4, 64), 256>>>(
        h1h, w2h, b2, 0, hh, E_, 256, 256, 0, 0, 0);
    // #5: qkv -> qkh (Q scaled + K), vh (V transposed)
    hgemm_kernel<false, false, true,  false><<<dim3(12, 64), 256>>>(
        hh, ipwh, ipb, 0, 0, E_, 768, 256, 0, qkh, vh);

    // #6: flash (ncu -s 5 -c 1 captures this launch)
    flash_attn_mma_kernel<<<dim3(32, 8), 256, FLASH_SMEM>>>(qkh, vh, mb, oh);

    // #7: node = x @ root + bias_p
    hgemm_kernel<false, false, false, false><<<dim3(4, 32), 256>>>(
        xh, rooth, bp, node, 0, NN_, 256, 256, 0, 0, 0);
    // #8: node[ei[1][e]] += o @ out_w^T + out_b  (fused scatter)
    hgemm_kernel<false, true,  false, false><<<dim3(4, 64), 256>>>(
        oh, owh, ob, node, 0, E_, 256, 256, ei, 0, 0);

    // #9
    ln_kernel<<<NN_, 256>>>(node, l1g, l1b, y, yh);
    // #10: z = y @ lin_w^T + lin_b
    hgemm_kernel<false, false, false, false><<<dim3(4, 32), 256>>>(
        yh, lwh, lb, z, 0, NN_, 256, 256, 0, 0, 0);
    // #11
    ln_add_kernel<<<NN_, 256>>>(y, z, l2g, l2b, out);
}